// round 14
// baseline (speedup 1.0000x reference)
#include <cuda_runtime.h>

#define NQ  10
#define DIM 1024
#define NL  4
#define TPB 64

typedef unsigned long long u64;

// Hardcoded GF(2) swizzle matrices (fixed CNOT rings; rank-5 verified store+gather).
#define A0_3 9u
#define A1_3 0x11u
#define A1_4 1u
#define PC0  0x200u
#define PC1  0x201u

// compact gate layout per layer (55 u64):
//   [0..7]   q0 merged-gather coeffs {c00,d00,c01,d01, c11,d11,c10,d10}
//   [8+3(q-1)] q1..q5: {C, Sp, Sn}
//   [23+8(q-6)] q6..q9: full 8-pack
#define GL 55

__device__ __align__(16) u64 g_gmat2[NL * GL + 1];
__device__ __align__(16) u64 g_pp[NL][32][4];        // {preC,preD,postC,postD}

// addr columns of gather index (addr(Finv(j))) per j bit, derived by hand:
// type0 Finv: y_k = x_k^x_{k+1} (k<=7), y8 = x8^x9^x0, y9 = x9^x0
// type1 Finv: y0..4 = x5..9, y5+k = x5+k^xk
// addr(y) = y ^ Amul(y>>5) (A0 cols {1,2,4,9,0}; A1 cols {2,4,8,0x11,1})
__device__ __constant__ const unsigned c_dummy = 0; // (no constant bank needed; all immediates)

__device__ __forceinline__ u64 pack2(float x, float y) {
    u64 r; asm("mov.b64 %0, {%1,%2};" : "=l"(r) : "f"(x), "f"(y)); return r;
}
__device__ __forceinline__ void unpk(u64 v, float& x, float& y) {
    asm("mov.b64 {%0,%1}, %2;" : "=f"(x), "=f"(y) : "l"(v));
}
__device__ __forceinline__ u64 swp(u64 v) {
    u64 r;
    asm("{\n\t.reg .b32 lo, hi;\n\tmov.b64 {lo,hi}, %1;\n\tmov.b64 %0, {hi,lo};\n\t}"
        : "=l"(r) : "l"(v));
    return r;
}
__device__ __forceinline__ u64 ffma2(u64 a, u64 b, u64 c) {
    u64 d; asm("fma.rn.f32x2 %0, %1, %2, %3;" : "=l"(d) : "l"(a), "l"(b), "l"(c)); return d;
}
__device__ __forceinline__ u64 fmul2(u64 a, u64 b) {
    u64 d; asm("mul.rn.f32x2 %0, %1, %2;" : "=l"(d) : "l"(a), "l"(b)); return d;
}
__device__ __forceinline__ u64 fadd2(u64 a, u64 b) {
    u64 d; asm("add.rn.f32x2 %0, %1, %2;" : "=l"(d) : "l"(a), "l"(b)); return d;
}
__device__ __forceinline__ float2 cmulf(float2 a, float2 b) {
    return make_float2(a.x * b.x - a.y * b.y, a.x * b.y + a.y * b.x);
}

__global__ void precompute_kernel(const float* __restrict__ w) {
    int t = threadIdx.x;

    // fused variational gates (compact layout)
    if (t < NL * NQ) {
        int l = t / NQ, q = t % NQ;
        float w0 = w[t * 3 + 0], w1 = w[t * 3 + 1], w2 = w[t * 3 + 2];
        float sb, cb; sincosf(0.5f * w1, &sb, &cb);
        if (q >= 1 && q <= 5) {
            u64* g = &g_gmat2[l * GL + 8 + (q - 1) * 3];
            g[0] = pack2(cb, cb);
            g[1] = pack2(sb, sb);
            g[2] = pack2(-sb, -sb);
        } else {
            float sp, cp; sincosf(0.5f * (w0 + w2), &sp, &cp);
            float sd, cd; sincosf(0.5f * (w0 - w2), &sd, &cd);
            float ar = cb * cp, ai = -cb * sp;   // U00
            float br = sb * cd, bi = -sb * sd;   // U10 ; U01=-conj(U10), U11=conj(U00)
            if (q == 0) {
                u64* g = &g_gmat2[l * GL];
                g[0] = pack2(ar, ar);   g[1] = pack2(-ai, ai);
                g[2] = pack2(-br, -br); g[3] = pack2(-bi, bi);
                g[4] = pack2(ar, ar);   g[5] = pack2(ai, -ai);
                g[6] = pack2(br, br);   g[7] = pack2(-bi, bi);
            } else {
                u64* g = &g_gmat2[l * GL + 23 + (q - 6) * 8];
                g[0] = pack2(ar, ar);   g[1] = pack2(-ai, ai);
                g[2] = pack2(-br, -br); g[3] = pack2(-bi, bi);
                g[4] = pack2(br, br);   g[5] = pack2(-bi, bi);
                g[6] = pack2(ar, ar);   g[7] = pack2(ai, -ai);
            }
        }
    }
    if (t == 0) g_gmat2[NL * GL] = 0;

    // per-(layer,lane) pre/post phase scalar packs
    {
        int l = t >> 5, lane = t & 31;
        float2 pre = make_float2(1.0f, 0.0f), post = make_float2(1.0f, 0.0f);
        #pragma unroll
        for (int q = 1; q <= 5; ++q) {
            float w0 = w[(l * NQ + q) * 3 + 0];
            float w2 = w[(l * NQ + q) * 3 + 2];
            float s0, c0; sincosf(0.5f * w0, &s0, &c0);
            float s2, c2; sincosf(0.5f * w2, &s2, &c2);
            float py = -s0, oy = -s2;
            if ((lane >> (5 - q)) & 1) { py = -py; oy = -oy; }
            pre  = cmulf(pre,  make_float2(c0, py));
            post = cmulf(post, make_float2(c2, oy));
        }
        g_pp[l][lane][0] = pack2(pre.x, pre.x);
        g_pp[l][lane][1] = pack2(-pre.y, pre.y);
        g_pp[l][lane][2] = pack2(post.x, post.x);
        g_pp[l][lane][3] = pack2(-post.y, post.y);
    }
}

// full-complex gate on k-bit mask M over 16 packed-complex amps
template<int M>
__device__ __forceinline__ void gate_reg(u64* r, const u64* __restrict__ C) {
    const u64 c00 = C[0], d00 = C[1], c01 = C[2], d01 = C[3];
    const u64 c10 = C[4], d10 = C[5], c11 = C[6], d11 = C[7];
    #pragma unroll
    for (int k = 0; k < 16; ++k) {
        if ((k & M) == 0) {
            const int k1 = k | M;
            u64 a0 = r[k], a1 = r[k1];
            u64 s0 = swp(a0), s1 = swp(a1);
            r[k]  = ffma2(c00, a0, ffma2(d00, s0, ffma2(c01, a1, fmul2(d01, s1))));
            r[k1] = ffma2(c10, a0, ffma2(d10, s0, ffma2(c11, a1, fmul2(d11, s1))));
        }
    }
}

// real RY butterfly on lane-bit xor distance D
template<int D>
__device__ __forceinline__ void ry_shfl(u64* r, u64 cc, u64 ss) {
    #pragma unroll
    for (int k = 0; k < 16; ++k) {
        u64 own = r[k];
        u64 par = __shfl_xor_sync(0xffffffffu, own, D);
        r[k] = ffma2(ss, par, fmul2(cc, own));
    }
}

// per-thread diagonal phase pass
__device__ __forceinline__ void phase_pass(u64* r, u64 C, u64 D) {
    #pragma unroll
    for (int k = 0; k < 16; ++k)
        r[k] = ffma2(C, r[k], fmul2(D, swp(r[k])));
}

__device__ __forceinline__ u64 pair_apply(u64 a, u64 p, u64 cA, u64 dA, u64 cB, u64 dB) {
    return ffma2(cA, a, ffma2(dA, swp(a), ffma2(cB, p, fmul2(dB, swp(p)))));
}

// One variational layer: gates + store + compile-time-indexed gather
template<int PAR, bool LAST>
__device__ __forceinline__ void layer_body(u64* r, u64* sc, const u64* __restrict__ GB,
                                           const u64* __restrict__ pp,
                                           unsigned addrC, unsigned Bg, int lane, int w) {
    // qubits 6..9: full complex gates on k bits
    gate_reg<8>(r, GB + 23);
    gate_reg<4>(r, GB + 31);
    gate_reg<2>(r, GB + 39);
    gate_reg<1>(r, GB + 47);

    // qubits 1..5 diagonalized
    phase_pass(r, pp[0], pp[1]);
    ry_shfl<16>(r, GB[8],  (lane & 16) ? GB[9]  : GB[10]);
    ry_shfl<8>(r, GB[11], (lane & 8)  ? GB[12] : GB[13]);
    ry_shfl<4>(r, GB[14], (lane & 4)  ? GB[15] : GB[16]);
    ry_shfl<2>(r, GB[17], (lane & 2)  ? GB[18] : GB[19]);
    ry_shfl<1>(r, GB[20], (lane & 1)  ? GB[21] : GB[22]);
    if (!LAST) phase_pass(r, pp[2], pp[3]);   // last layer: post-diag invisible to |amp|^2

    // store (A-swizzled, conflict-free)
    #pragma unroll
    for (int k = 0; k < 16; ++k)
        sc[addrC ^ (unsigned)k] = r[k];
    __syncthreads();

    // gather: idx = Bg ^ K[2c+h] (GF(2)-linear, all immediates)
    constexpr unsigned PC = PAR ? PC1 : PC0;
    constexpr unsigned K0[16] = {0x000,0x308, 0x003,0x30B, 0x006,0x30E, 0x005,0x30D,
                                 0x00C,0x304, 0x00F,0x307, 0x00A,0x302, 0x009,0x301};
    constexpr unsigned K1[16] = {0x000,0x022, 0x044,0x066, 0x088,0x0AA, 0x0CC,0x0EE,
                                 0x111,0x133, 0x155,0x177, 0x199,0x1BB, 0x1DD,0x1FF};
    const u64 q0_0 = GB[0], q0_1 = GB[1], q0_2 = GB[2], q0_3 = GB[3];
    const u64 q1_0 = GB[4], q1_1 = GB[5], q1_2 = GB[6], q1_3 = GB[7];

    if (PAR == 0) {
        // bb = w ^ h : static per h-branch
        const bool bw = (w != 0);
        const u64 cA0 = bw ? q1_0 : q0_0, dA0 = bw ? q1_1 : q0_1;
        const u64 cB0 = bw ? q1_2 : q0_2, dB0 = bw ? q1_3 : q0_3;
        const u64 cA1 = bw ? q0_0 : q1_0, dA1 = bw ? q0_1 : q1_1;
        const u64 cB1 = bw ? q0_2 : q1_2, dB1 = bw ? q0_3 : q1_3;
        #pragma unroll
        for (int c = 0; c < 8; ++c) {
            unsigned i0 = Bg ^ K0[2 * c];
            unsigned i1 = Bg ^ K0[2 * c + 1];
            r[2 * c]     = pair_apply(sc[i0], sc[i0 ^ PC], cA0, dA0, cB0, dB0);
            r[2 * c + 1] = pair_apply(sc[i1], sc[i1 ^ PC], cA1, dA1, cB1, dB1);
        }
    } else {
        // bb = w ^ lane0 : one select per layer
        const bool bb = (((lane ^ w) & 1) != 0);
        const u64 cA = bb ? q1_0 : q0_0, dA = bb ? q1_1 : q0_1;
        const u64 cB = bb ? q1_2 : q0_2, dB = bb ? q1_3 : q0_3;
        #pragma unroll
        for (int i = 0; i < 16; ++i) {
            unsigned idx = Bg ^ K1[i];
            r[i] = pair_apply(sc[idx], sc[idx ^ PC], cA, dA, cB, dB);
        }
    }
    __syncthreads();
}

__global__ __launch_bounds__(TPB, 12) void qsim_kernel(
    const float* __restrict__ x,     // (B, 2*NQ)
    float* __restrict__ out)         // (B, NQ)
{
    __shared__ __align__(16) u64 sc[DIM];             // 8 KB state scratch
    __shared__ __align__(16) u64 gmat_s[NL * GL + 1]; // 1.77 KB compact gates
    __shared__ __align__(16) u64 pp_s[NL][32][4];     // 4 KB phase packs
    __shared__ float2 venc[NQ][2];
    __shared__ float red[2][NQ];

    const int t    = threadIdx.x;
    const int lane = t & 31;
    const int w    = t >> 5;                   // warp half = qubit-0 bit (j9)
    const int s    = blockIdx.x;
    const float inv_sqrt2 = 0.70710678118654752440f;
    const float pi_f      = 3.14159265358979323846f;

    // vectorized table copies
    {
        const uint4* gs = (const uint4*)&g_gmat2[0];
        uint4* gd = (uint4*)&gmat_s[0];
        #pragma unroll
        for (int i = t; i < (NL * GL + 1) / 2; i += TPB) gd[i] = gs[i];
        const uint4* ps = (const uint4*)&g_pp[0][0][0];
        uint4* pd = (uint4*)&pp_s[0][0][0];
        #pragma unroll
        for (int i = t; i < 256; i += TPB) pd[i] = ps[i];
    }

    // per-thread store-address constants (amul hardcoded: A0·jhi, A1·jhi)
    const unsigned jhi = (unsigned)(w * 16 + (lane >> 1));
    unsigned am0 = 0, am1 = 0;
    {
        if (jhi & 1u)  { am0 ^= 1u;    am1 ^= 2u; }
        if (jhi & 2u)  { am0 ^= 2u;    am1 ^= 4u; }
        if (jhi & 4u)  { am0 ^= 4u;    am1 ^= 8u; }
        if (jhi & 8u)  { am0 ^= A0_3;  am1 ^= A1_3; }
        if (jhi & 16u) {               am1 ^= A1_4; }
    }
    const unsigned addrC0 = (jhi << 5) | (((unsigned)(lane & 1) << 4) ^ am0);
    const unsigned addrC1 = (jhi << 5) | (((unsigned)(lane & 1) << 4) ^ am1);

    // per-thread gather bases: XOR of addr-columns for lane bits (j4..j8) and w (j9)
    unsigned B0 = 0, B1 = 0;
    {
        if (lane & 1)  { B0 ^= 0x018u; B1 ^= 0x201u; }
        if (lane & 2)  { B0 ^= 0x031u; B1 ^= 0x023u; }
        if (lane & 4)  { B0 ^= 0x063u; B1 ^= 0x046u; }
        if (lane & 8)  { B0 ^= 0x0C6u; B1 ^= 0x08Cu; }
        if (lane & 16) { B0 ^= 0x18Du; B1 ^= 0x119u; }
        if (w)         { B0 ^= 0x309u; B1 ^= 0x211u; }
    }

    if (t < NQ) {
        int q = t;
        float th = 0.5f * pi_f * (x[s * 2 * NQ + q]      + 1.0f);
        float ph = 0.5f * pi_f * (x[s * 2 * NQ + NQ + q] + 1.0f);
        float st, ct; sincosf(0.5f * th, &st, &ct);
        float sh, ch; sincosf(0.5f * ph, &sh, &ch);
        float a = inv_sqrt2 * (ct - st);
        float b = inv_sqrt2 * (ct + st);
        venc[q][0] = make_float2(a * ch, -a * sh);
        venc[q][1] = make_float2(b * ch,  b * sh);
    }
    __syncthreads();

    // ---- build product state: j = w*512 + lane*16 + k ; qubit q <-> j bit (9-q) ----
    u64 r[16];
    {
        float2 L = venc[0][w];
        L = cmulf(L, venc[1][(lane >> 4) & 1]);
        L = cmulf(L, venc[2][(lane >> 3) & 1]);
        L = cmulf(L, venc[3][(lane >> 2) & 1]);
        L = cmulf(L, venc[4][(lane >> 1) & 1]);
        L = cmulf(L, venc[5][lane & 1]);
        float2 RH[4], RL[4];
        #pragma unroll
        for (int h = 0; h < 4; ++h) RH[h] = cmulf(venc[6][(h >> 1) & 1], venc[7][h & 1]);
        #pragma unroll
        for (int l = 0; l < 4; ++l) RL[l] = cmulf(venc[8][(l >> 1) & 1], venc[9][l & 1]);
        #pragma unroll
        for (int k = 0; k < 16; ++k) {
            float2 a = cmulf(L, cmulf(RH[k >> 2], RL[k & 3]));
            r[k] = pack2(a.x, a.y);
        }
    }

    // ---- 4 layers, fully unrolled (parity constants immediate) ----
    layer_body<0, false>(r, sc, &gmat_s[0 * GL], pp_s[0][lane], addrC0, B0, lane, w);
    layer_body<1, false>(r, sc, &gmat_s[1 * GL], pp_s[1][lane], addrC1, B1, lane, w);
    layer_body<0, false>(r, sc, &gmat_s[2 * GL], pp_s[2][lane], addrC0, B0, lane, w);
    layer_body<1, true >(r, sc, &gmat_s[3 * GL], pp_s[3][lane], addrC1, B1, lane, w);

    // ---- <Z_q> readout ----
    u64 tot = 0, accP[4] = {0,0,0,0}, accN[4] = {0,0,0,0};
    #pragma unroll
    for (int k = 0; k < 16; ++k) {
        u64 sq = fmul2(r[k], r[k]);          // (re^2, im^2)
        tot = fadd2(tot, sq);
        #pragma unroll
        for (int b = 0; b < 4; ++b) {
            if ((k >> b) & 1) accN[b] = fadd2(accN[b], sq);
            else              accP[b] = fadd2(accP[b], sq);
        }
    }
    float zq[NQ];
    {
        float tl, th; unpk(tot, tl, th);
        float pr_tot = tl + th;
        zq[0] = w ? -pr_tot : pr_tot;
        zq[1] = (lane & 16) ? -pr_tot : pr_tot;
        zq[2] = (lane & 8)  ? -pr_tot : pr_tot;
        zq[3] = (lane & 4)  ? -pr_tot : pr_tot;
        zq[4] = (lane & 2)  ? -pr_tot : pr_tot;
        zq[5] = (lane & 1)  ? -pr_tot : pr_tot;
        #pragma unroll
        for (int b = 0; b < 4; ++b) {        // k bit b <-> qubit 9-b
            float pl, ph, nl, nh;
            unpk(accP[b], pl, ph); unpk(accN[b], nl, nh);
            zq[9 - b] = (pl + ph) - (nl + nh);
        }
    }
    #pragma unroll
    for (int q = 0; q < NQ; ++q) {
        #pragma unroll
        for (int o = 16; o > 0; o >>= 1)
            zq[q] += __shfl_xor_sync(0xffffffffu, zq[q], o);
    }
    if (lane == 0) {
        #pragma unroll
        for (int q = 0; q < NQ; ++q) red[w][q] = zq[q];
    }
    __syncthreads();
    if (t < NQ)
        out[s * NQ + t] = red[0][t] + red[1][t];
}

extern "C" void kernel_launch(void* const* d_in, const int* in_sizes, int n_in,
                              void* d_out, int out_size) {
    const float* x = (const float*)d_in[0];
    const float* w = (const float*)d_in[1];
    float* out = (float*)d_out;
    int B = in_sizes[0] / (2 * NQ);   // 4096 flattened samples
    precompute_kernel<<<1, 128>>>(w);
    qsim_kernel<<<B, TPB>>>(x, out);
}

// round 15
// speedup vs baseline: 1.1364x; 1.1364x over previous
#include <cuda_runtime.h>

#define NQ  10
#define DIM 1024
#define NL  4
#define TPB 64

typedef unsigned long long u64;

// Hardcoded GF(2) swizzle matrices (fixed CNOT rings; rank-5 verified store+gather).
#define A0_3 9u
#define A1_3 0x11u
#define A1_4 1u
#define PC0  0x200u
#define PC1  0x201u

// compact gate layout per layer (55 u64):
//   [0..7]   q0 merged-gather coeffs {c00,d00,c01,d01, c11,d11,c10,d10}
//   [8+3(q-1)] q1..q5: {C, Sp, Sn}
//   [23+8(q-6)] q6..q9: full 8-pack
#define GL 55

__device__ __align__(16) u64 g_gmat2[NL * GL + 1];
__device__ __align__(16) u64 g_pp[NL][32][4];        // {preC,preD,postC,postD}

__device__ __forceinline__ u64 pack2(float x, float y) {
    u64 r; asm("mov.b64 %0, {%1,%2};" : "=l"(r) : "f"(x), "f"(y)); return r;
}
__device__ __forceinline__ void unpk(u64 v, float& x, float& y) {
    asm("mov.b64 {%0,%1}, %2;" : "=f"(x), "=f"(y) : "l"(v));
}
__device__ __forceinline__ u64 swp(u64 v) {
    u64 r;
    asm("{\n\t.reg .b32 lo, hi;\n\tmov.b64 {lo,hi}, %1;\n\tmov.b64 %0, {hi,lo};\n\t}"
        : "=l"(r) : "l"(v));
    return r;
}
__device__ __forceinline__ u64 ffma2(u64 a, u64 b, u64 c) {
    u64 d; asm("fma.rn.f32x2 %0, %1, %2, %3;" : "=l"(d) : "l"(a), "l"(b), "l"(c)); return d;
}
__device__ __forceinline__ u64 fmul2(u64 a, u64 b) {
    u64 d; asm("mul.rn.f32x2 %0, %1, %2;" : "=l"(d) : "l"(a), "l"(b)); return d;
}
__device__ __forceinline__ u64 fadd2(u64 a, u64 b) {
    u64 d; asm("add.rn.f32x2 %0, %1, %2;" : "=l"(d) : "l"(a), "l"(b)); return d;
}
__device__ __forceinline__ float2 cmulf(float2 a, float2 b) {
    return make_float2(a.x * b.x - a.y * b.y, a.x * b.y + a.y * b.x);
}

__global__ void precompute_kernel(const float* __restrict__ w) {
    int t = threadIdx.x;

    // fused variational gates (compact layout)
    if (t < NL * NQ) {
        int l = t / NQ, q = t % NQ;
        float w0 = w[t * 3 + 0], w1 = w[t * 3 + 1], w2 = w[t * 3 + 2];
        float sb, cb; sincosf(0.5f * w1, &sb, &cb);
        if (q >= 1 && q <= 5) {
            u64* g = &g_gmat2[l * GL + 8 + (q - 1) * 3];
            g[0] = pack2(cb, cb);
            g[1] = pack2(sb, sb);
            g[2] = pack2(-sb, -sb);
        } else {
            float sp, cp; sincosf(0.5f * (w0 + w2), &sp, &cp);
            float sd, cd; sincosf(0.5f * (w0 - w2), &sd, &cd);
            float ar = cb * cp, ai = -cb * sp;   // U00
            float br = sb * cd, bi = -sb * sd;   // U10 ; U01=-conj(U10), U11=conj(U00)
            if (q == 0) {
                u64* g = &g_gmat2[l * GL];
                g[0] = pack2(ar, ar);   g[1] = pack2(-ai, ai);
                g[2] = pack2(-br, -br); g[3] = pack2(-bi, bi);
                g[4] = pack2(ar, ar);   g[5] = pack2(ai, -ai);
                g[6] = pack2(br, br);   g[7] = pack2(-bi, bi);
            } else {
                u64* g = &g_gmat2[l * GL + 23 + (q - 6) * 8];
                g[0] = pack2(ar, ar);   g[1] = pack2(-ai, ai);
                g[2] = pack2(-br, -br); g[3] = pack2(-bi, bi);
                g[4] = pack2(br, br);   g[5] = pack2(-bi, bi);
                g[6] = pack2(ar, ar);   g[7] = pack2(ai, -ai);
            }
        }
    }
    if (t == 0) g_gmat2[NL * GL] = 0;

    // per-(layer,lane) pre/post phase scalar packs
    {
        int l = t >> 5, lane = t & 31;
        float2 pre = make_float2(1.0f, 0.0f), post = make_float2(1.0f, 0.0f);
        #pragma unroll
        for (int q = 1; q <= 5; ++q) {
            float w0 = w[(l * NQ + q) * 3 + 0];
            float w2 = w[(l * NQ + q) * 3 + 2];
            float s0, c0; sincosf(0.5f * w0, &s0, &c0);
            float s2, c2; sincosf(0.5f * w2, &s2, &c2);
            float py = -s0, oy = -s2;
            if ((lane >> (5 - q)) & 1) { py = -py; oy = -oy; }
            pre  = cmulf(pre,  make_float2(c0, py));
            post = cmulf(post, make_float2(c2, oy));
        }
        g_pp[l][lane][0] = pack2(pre.x, pre.x);
        g_pp[l][lane][1] = pack2(-pre.y, pre.y);
        g_pp[l][lane][2] = pack2(post.x, post.x);
        g_pp[l][lane][3] = pack2(-post.y, post.y);
    }
}

// full-complex gate on k-bit mask M over 16 packed-complex amps
template<int M>
__device__ __forceinline__ void gate_reg(u64* r, const u64* __restrict__ C) {
    const u64 c00 = C[0], d00 = C[1], c01 = C[2], d01 = C[3];
    const u64 c10 = C[4], d10 = C[5], c11 = C[6], d11 = C[7];
    #pragma unroll
    for (int k = 0; k < 16; ++k) {
        if ((k & M) == 0) {
            const int k1 = k | M;
            u64 a0 = r[k], a1 = r[k1];
            u64 s0 = swp(a0), s1 = swp(a1);
            r[k]  = ffma2(c00, a0, ffma2(d00, s0, ffma2(c01, a1, fmul2(d01, s1))));
            r[k1] = ffma2(c10, a0, ffma2(d10, s0, ffma2(c11, a1, fmul2(d11, s1))));
        }
    }
}

// real RY butterfly on lane-bit xor distance D
template<int D>
__device__ __forceinline__ void ry_shfl(u64* r, u64 cc, u64 ss) {
    #pragma unroll
    for (int k = 0; k < 16; ++k) {
        u64 own = r[k];
        u64 par = __shfl_xor_sync(0xffffffffu, own, D);
        r[k] = ffma2(ss, par, fmul2(cc, own));
    }
}

// per-thread diagonal phase pass
__device__ __forceinline__ void phase_pass(u64* r, u64 C, u64 D) {
    #pragma unroll
    for (int k = 0; k < 16; ++k)
        r[k] = ffma2(C, r[k], fmul2(D, swp(r[k])));
}

__device__ __forceinline__ u64 pair_apply(u64 a, u64 p, u64 cA, u64 dA, u64 cB, u64 dB) {
    return ffma2(cA, a, ffma2(dA, swp(a), ffma2(cB, p, fmul2(dB, swp(p)))));
}

// One variational layer: gates + store + compile-time-indexed gather.
// skip_post: runtime flag (true only for the very last layer).
template<int PAR>
__device__ __forceinline__ void layer_body(u64* r, u64* sc, const u64* __restrict__ GB,
                                           const u64* __restrict__ pp,
                                           unsigned addrC, unsigned Bg, int lane, int w,
                                           bool skip_post) {
    // qubits 6..9: full complex gates on k bits
    gate_reg<8>(r, GB + 23);
    gate_reg<4>(r, GB + 31);
    gate_reg<2>(r, GB + 39);
    gate_reg<1>(r, GB + 47);

    // qubits 1..5 diagonalized
    phase_pass(r, pp[0], pp[1]);
    ry_shfl<16>(r, GB[8],  (lane & 16) ? GB[9]  : GB[10]);
    ry_shfl<8>(r, GB[11], (lane & 8)  ? GB[12] : GB[13]);
    ry_shfl<4>(r, GB[14], (lane & 4)  ? GB[15] : GB[16]);
    ry_shfl<2>(r, GB[17], (lane & 2)  ? GB[18] : GB[19]);
    ry_shfl<1>(r, GB[20], (lane & 1)  ? GB[21] : GB[22]);
    if (!skip_post) phase_pass(r, pp[2], pp[3]);   // last layer: invisible to |amp|^2

    // store (A-swizzled, conflict-free)
    #pragma unroll
    for (int k = 0; k < 16; ++k)
        sc[addrC ^ (unsigned)k] = r[k];
    __syncthreads();

    // gather: idx = Bg ^ K[i] (GF(2)-linear, all immediates)
    constexpr unsigned PC = PAR ? PC1 : PC0;
    constexpr unsigned K0[16] = {0x000,0x308, 0x003,0x30B, 0x006,0x30E, 0x005,0x30D,
                                 0x00C,0x304, 0x00F,0x307, 0x00A,0x302, 0x009,0x301};
    constexpr unsigned K1[16] = {0x000,0x022, 0x044,0x066, 0x088,0x0AA, 0x0CC,0x0EE,
                                 0x111,0x133, 0x155,0x177, 0x199,0x1BB, 0x1DD,0x1FF};
    const u64 q0_0 = GB[0], q0_1 = GB[1], q0_2 = GB[2], q0_3 = GB[3];
    const u64 q1_0 = GB[4], q1_1 = GB[5], q1_2 = GB[6], q1_3 = GB[7];

    if (PAR == 0) {
        // bb = w ^ h : static per h-branch
        const bool bw = (w != 0);
        const u64 cA0 = bw ? q1_0 : q0_0, dA0 = bw ? q1_1 : q0_1;
        const u64 cB0 = bw ? q1_2 : q0_2, dB0 = bw ? q1_3 : q0_3;
        const u64 cA1 = bw ? q0_0 : q1_0, dA1 = bw ? q0_1 : q1_1;
        const u64 cB1 = bw ? q0_2 : q1_2, dB1 = bw ? q0_3 : q1_3;
        #pragma unroll
        for (int c = 0; c < 8; ++c) {
            unsigned i0 = Bg ^ K0[2 * c];
            unsigned i1 = Bg ^ K0[2 * c + 1];
            r[2 * c]     = pair_apply(sc[i0], sc[i0 ^ PC], cA0, dA0, cB0, dB0);
            r[2 * c + 1] = pair_apply(sc[i1], sc[i1 ^ PC], cA1, dA1, cB1, dB1);
        }
    } else {
        // bb = w ^ lane0 : one select per layer
        const bool bb = (((lane ^ w) & 1) != 0);
        const u64 cA = bb ? q1_0 : q0_0, dA = bb ? q1_1 : q0_1;
        const u64 cB = bb ? q1_2 : q0_2, dB = bb ? q1_3 : q0_3;
        #pragma unroll
        for (int i = 0; i < 16; ++i) {
            unsigned idx = Bg ^ K1[i];
            r[i] = pair_apply(sc[idx], sc[idx ^ PC], cA, dA, cB, dB);
        }
    }
    __syncthreads();
}

__global__ __launch_bounds__(TPB, 12) void qsim_kernel(
    const float* __restrict__ x,     // (B, 2*NQ)
    float* __restrict__ out)         // (B, NQ)
{
    __shared__ __align__(16) u64 sc[DIM];             // 8 KB state scratch
    __shared__ __align__(16) u64 gmat_s[NL * GL + 1]; // 1.77 KB compact gates
    __shared__ __align__(16) u64 pp_s[NL][32][4];     // 4 KB phase packs
    __shared__ float2 venc[NQ][2];
    __shared__ float red[2][NQ];

    const int t    = threadIdx.x;
    const int lane = t & 31;
    const int w    = t >> 5;                   // warp half = qubit-0 bit (j9)
    const int s    = blockIdx.x;
    const float inv_sqrt2 = 0.70710678118654752440f;
    const float pi_f      = 3.14159265358979323846f;

    // vectorized table copies
    {
        const uint4* gs = (const uint4*)&g_gmat2[0];
        uint4* gd = (uint4*)&gmat_s[0];
        #pragma unroll
        for (int i = t; i < (NL * GL + 1) / 2; i += TPB) gd[i] = gs[i];
        const uint4* ps = (const uint4*)&g_pp[0][0][0];
        uint4* pd = (uint4*)&pp_s[0][0][0];
        #pragma unroll
        for (int i = t; i < 256; i += TPB) pd[i] = ps[i];
    }

    // per-thread store-address constants (amul hardcoded: A0·jhi, A1·jhi)
    const unsigned jhi = (unsigned)(w * 16 + (lane >> 1));
    unsigned am0 = 0, am1 = 0;
    {
        if (jhi & 1u)  { am0 ^= 1u;    am1 ^= 2u; }
        if (jhi & 2u)  { am0 ^= 2u;    am1 ^= 4u; }
        if (jhi & 4u)  { am0 ^= 4u;    am1 ^= 8u; }
        if (jhi & 8u)  { am0 ^= A0_3;  am1 ^= A1_3; }
        if (jhi & 16u) {               am1 ^= A1_4; }
    }
    const unsigned addrC0 = (jhi << 5) | (((unsigned)(lane & 1) << 4) ^ am0);
    const unsigned addrC1 = (jhi << 5) | (((unsigned)(lane & 1) << 4) ^ am1);

    // per-thread gather bases: XOR of addr-columns for lane bits (j4..j8) and w (j9)
    unsigned B0 = 0, B1 = 0;
    {
        if (lane & 1)  { B0 ^= 0x018u; B1 ^= 0x201u; }
        if (lane & 2)  { B0 ^= 0x031u; B1 ^= 0x023u; }
        if (lane & 4)  { B0 ^= 0x063u; B1 ^= 0x046u; }
        if (lane & 8)  { B0 ^= 0x0C6u; B1 ^= 0x08Cu; }
        if (lane & 16) { B0 ^= 0x18Du; B1 ^= 0x119u; }
        if (w)         { B0 ^= 0x309u; B1 ^= 0x211u; }
    }

    if (t < NQ) {
        int q = t;
        float th = 0.5f * pi_f * (x[s * 2 * NQ + q]      + 1.0f);
        float ph = 0.5f * pi_f * (x[s * 2 * NQ + NQ + q] + 1.0f);
        float st, ct; sincosf(0.5f * th, &st, &ct);
        float sh, ch; sincosf(0.5f * ph, &sh, &ch);
        float a = inv_sqrt2 * (ct - st);
        float b = inv_sqrt2 * (ct + st);
        venc[q][0] = make_float2(a * ch, -a * sh);
        venc[q][1] = make_float2(b * ch,  b * sh);
    }
    __syncthreads();

    // ---- build product state: j = w*512 + lane*16 + k ; qubit q <-> j bit (9-q) ----
    u64 r[16];
    {
        float2 L = venc[0][w];
        L = cmulf(L, venc[1][(lane >> 4) & 1]);
        L = cmulf(L, venc[2][(lane >> 3) & 1]);
        L = cmulf(L, venc[3][(lane >> 2) & 1]);
        L = cmulf(L, venc[4][(lane >> 1) & 1]);
        L = cmulf(L, venc[5][lane & 1]);
        float2 RH[4], RL[4];
        #pragma unroll
        for (int h = 0; h < 4; ++h) RH[h] = cmulf(venc[6][(h >> 1) & 1], venc[7][h & 1]);
        #pragma unroll
        for (int l = 0; l < 4; ++l) RL[l] = cmulf(venc[8][(l >> 1) & 1], venc[9][l & 1]);
        #pragma unroll
        for (int k = 0; k < 16; ++k) {
            float2 a = cmulf(L, cmulf(RH[k >> 2], RL[k & 3]));
            r[k] = pack2(a.x, a.y);
        }
    }

    // ---- layers: loop over layer-PAIRS (body ~2 layers ≈ 20KB, fits L1.5 I$) ----
    #pragma unroll 1
    for (int it = 0; it < 2; ++it) {
        const int l0 = 2 * it, l1 = 2 * it + 1;
        layer_body<0>(r, sc, &gmat_s[l0 * GL], pp_s[l0][lane], addrC0, B0, lane, w, false);
        layer_body<1>(r, sc, &gmat_s[l1 * GL], pp_s[l1][lane], addrC1, B1, lane, w, it == 1);
    }

    // ---- <Z_q> readout ----
    u64 tot = 0, accP[4] = {0,0,0,0}, accN[4] = {0,0,0,0};
    #pragma unroll
    for (int k = 0; k < 16; ++k) {
        u64 sq = fmul2(r[k], r[k]);          // (re^2, im^2)
        tot = fadd2(tot, sq);
        #pragma unroll
        for (int b = 0; b < 4; ++b) {
            if ((k >> b) & 1) accN[b] = fadd2(accN[b], sq);
            else              accP[b] = fadd2(accP[b], sq);
        }
    }
    float zq[NQ];
    {
        float tl, th; unpk(tot, tl, th);
        float pr_tot = tl + th;
        zq[0] = w ? -pr_tot : pr_tot;
        zq[1] = (lane & 16) ? -pr_tot : pr_tot;
        zq[2] = (lane & 8)  ? -pr_tot : pr_tot;
        zq[3] = (lane & 4)  ? -pr_tot : pr_tot;
        zq[4] = (lane & 2)  ? -pr_tot : pr_tot;
        zq[5] = (lane & 1)  ? -pr_tot : pr_tot;
        #pragma unroll
        for (int b = 0; b < 4; ++b) {        // k bit b <-> qubit 9-b
            float pl, ph, nl, nh;
            unpk(accP[b], pl, ph); unpk(accN[b], nl, nh);
            zq[9 - b] = (pl + ph) - (nl + nh);
        }
    }
    #pragma unroll
    for (int q = 0; q < NQ; ++q) {
        #pragma unroll
        for (int o = 16; o > 0; o >>= 1)
            zq[q] += __shfl_xor_sync(0xffffffffu, zq[q], o);
    }
    if (lane == 0) {
        #pragma unroll
        for (int q = 0; q < NQ; ++q) red[w][q] = zq[q];
    }
    __syncthreads();
    if (t < NQ)
        out[s * NQ + t] = red[0][t] + red[1][t];
}

extern "C" void kernel_launch(void* const* d_in, const int* in_sizes, int n_in,
                              void* d_out, int out_size) {
    const float* x = (const float*)d_in[0];
    const float* w = (const float*)d_in[1];
    float* out = (float*)d_out;
    int B = in_sizes[0] / (2 * NQ);   // 4096 flattened samples
    precompute_kernel<<<1, 128>>>(w);
    qsim_kernel<<<B, TPB>>>(x, out);
}

// round 16
// speedup vs baseline: 1.2168x; 1.0708x over previous
#include <cuda_runtime.h>

#define NQ  10
#define DIM 1024
#define NL  4
#define TPB 64

typedef unsigned long long u64;

// Hardcoded GF(2) swizzle matrices (fixed CNOT rings; rank-5 verified store+gather).
#define A0_3 9u
#define A1_3 0x11u
#define A1_4 1u
#define PC0  0x200u
#define PC1  0x201u

// compact gate layout per layer (55 u64):
//   [0..7]   q0 merged-gather coeffs {c00,d00,c01,d01, c11,d11,c10,d10}
//   [8+3(q-1)] q1..q5: {C, Sp, Sn}
//   [23+8(q-6)] q6..q9: full 8-pack
#define GL 55

__device__ __align__(16) u64 g_gmat2[NL * GL + 1];
__device__ __align__(16) u64 g_pp[NL][32][2];         // per-(layer,lane) pre packs {C,D}
__device__ __align__(16) u64 g_ppk[NL][2][16][2];     // per-(layer,b1,k) post packs {C,D}

__device__ __forceinline__ u64 pack2(float x, float y) {
    u64 r; asm("mov.b64 %0, {%1,%2};" : "=l"(r) : "f"(x), "f"(y)); return r;
}
__device__ __forceinline__ void unpk(u64 v, float& x, float& y) {
    asm("mov.b64 {%0,%1}, %2;" : "=f"(x), "=f"(y) : "l"(v));
}
__device__ __forceinline__ u64 swp(u64 v) {
    u64 r;
    asm("{\n\t.reg .b32 lo, hi;\n\tmov.b64 {lo,hi}, %1;\n\tmov.b64 %0, {hi,lo};\n\t}"
        : "=l"(r) : "l"(v));
    return r;
}
__device__ __forceinline__ u64 ffma2(u64 a, u64 b, u64 c) {
    u64 d; asm("fma.rn.f32x2 %0, %1, %2, %3;" : "=l"(d) : "l"(a), "l"(b), "l"(c)); return d;
}
__device__ __forceinline__ u64 fmul2(u64 a, u64 b) {
    u64 d; asm("mul.rn.f32x2 %0, %1, %2;" : "=l"(d) : "l"(a), "l"(b)); return d;
}
__device__ __forceinline__ u64 fadd2(u64 a, u64 b) {
    u64 d; asm("add.rn.f32x2 %0, %1, %2;" : "=l"(d) : "l"(a), "l"(b)); return d;
}
__device__ __forceinline__ float2 cmulf(float2 a, float2 b) {
    return make_float2(a.x * b.x - a.y * b.y, a.x * b.y + a.y * b.x);
}

__global__ void precompute_kernel(const float* __restrict__ w) {
    int t = threadIdx.x;

    // fused variational gates (compact layout)
    if (t < NL * NQ) {
        int l = t / NQ, q = t % NQ;
        float w0 = w[t * 3 + 0], w1 = w[t * 3 + 1], w2 = w[t * 3 + 2];
        float sb, cb; sincosf(0.5f * w1, &sb, &cb);
        if (q >= 1 && q <= 5) {
            u64* g = &g_gmat2[l * GL + 8 + (q - 1) * 3];
            g[0] = pack2(cb, cb);
            g[1] = pack2(sb, sb);
            g[2] = pack2(-sb, -sb);
        } else {
            float sp, cp; sincosf(0.5f * (w0 + w2), &sp, &cp);
            float sd, cd; sincosf(0.5f * (w0 - w2), &sd, &cd);
            float ar = cb * cp, ai = -cb * sp;   // U00
            float br = sb * cd, bi = -sb * sd;   // U10 ; U01=-conj(U10), U11=conj(U00)
            if (q == 0) {
                u64* g = &g_gmat2[l * GL];
                g[0] = pack2(ar, ar);   g[1] = pack2(-ai, ai);
                g[2] = pack2(-br, -br); g[3] = pack2(-bi, bi);
                g[4] = pack2(ar, ar);   g[5] = pack2(ai, -ai);
                g[6] = pack2(br, br);   g[7] = pack2(-bi, bi);
            } else {
                u64* g = &g_gmat2[l * GL + 23 + (q - 6) * 8];
                g[0] = pack2(ar, ar);   g[1] = pack2(-ai, ai);
                g[2] = pack2(-br, -br); g[3] = pack2(-bi, bi);
                g[4] = pack2(br, br);   g[5] = pack2(-bi, bi);
                g[6] = pack2(ar, ar);   g[7] = pack2(ai, -ai);
            }
        }
    }
    if (t == 0) g_gmat2[NL * GL] = 0;

    // per-(layer,lane) PRE phase packs (q1..5 RZ(w0) diag)
    {
        int l = t >> 5, lane = t & 31;
        float2 pre = make_float2(1.0f, 0.0f);
        #pragma unroll
        for (int q = 1; q <= 5; ++q) {
            float w0 = w[(l * NQ + q) * 3 + 0];
            float s0, c0; sincosf(0.5f * w0, &s0, &c0);
            float py = ((lane >> (5 - q)) & 1) ? s0 : -s0;
            pre = cmulf(pre, make_float2(c0, py));
        }
        g_pp[l][lane][0] = pack2(pre.x, pre.x);
        g_pp[l][lane][1] = pack2(-pre.y, pre.y);
    }

    // per-(layer,b1,k) POST phase packs: q1(b1) x q2..5(k bits 3..0) RZ(w2) diag
    {
        int l = t >> 5, b1 = (t >> 4) & 1, k = t & 15;
        float2 post;
        {
            float w2 = w[(l * NQ + 1) * 3 + 2];
            float s2, c2; sincosf(0.5f * w2, &s2, &c2);
            post = make_float2(c2, b1 ? s2 : -s2);
        }
        #pragma unroll
        for (int q = 2; q <= 5; ++q) {
            float w2 = w[(l * NQ + q) * 3 + 2];
            float s2, c2; sincosf(0.5f * w2, &s2, &c2);
            float oy = ((k >> (5 - q)) & 1) ? s2 : -s2;   // qubit q <-> k bit (5-q): q2->3..q5->0
            post = cmulf(post, make_float2(c2, oy));
        }
        g_ppk[l][b1][k][0] = pack2(post.x, post.x);
        g_ppk[l][b1][k][1] = pack2(-post.y, post.y);
    }
}

// full-complex gate on k-bit mask M over 16 packed-complex amps
template<int M>
__device__ __forceinline__ void gate_reg(u64* r, const u64* __restrict__ C) {
    const u64 c00 = C[0], d00 = C[1], c01 = C[2], d01 = C[3];
    const u64 c10 = C[4], d10 = C[5], c11 = C[6], d11 = C[7];
    #pragma unroll
    for (int k = 0; k < 16; ++k) {
        if ((k & M) == 0) {
            const int k1 = k | M;
            u64 a0 = r[k], a1 = r[k1];
            u64 s0 = swp(a0), s1 = swp(a1);
            r[k]  = ffma2(c00, a0, ffma2(d00, s0, ffma2(c01, a1, fmul2(d01, s1))));
            r[k1] = ffma2(c10, a0, ffma2(d10, s0, ffma2(c11, a1, fmul2(d11, s1))));
        }
    }
}

// real RY butterfly on k-bit mask M
template<int M>
__device__ __forceinline__ void ry_reg(u64* r, u64 C, u64 Sp, u64 Sn) {
    #pragma unroll
    for (int k = 0; k < 16; ++k) {
        if ((k & M) == 0) {
            const int k1 = k | M;
            u64 a0 = r[k], a1 = r[k1];
            r[k]  = ffma2(Sn, a1, fmul2(C, a0));
            r[k1] = ffma2(Sp, a0, fmul2(C, a1));
        }
    }
}

// real RY butterfly on lane-bit xor distance D
template<int D>
__device__ __forceinline__ void ry_shfl(u64* r, u64 cc, u64 ss) {
    #pragma unroll
    for (int k = 0; k < 16; ++k) {
        u64 own = r[k];
        u64 par = __shfl_xor_sync(0xffffffffu, own, D);
        r[k] = ffma2(ss, par, fmul2(cc, own));
    }
}

// per-thread diagonal phase pass
__device__ __forceinline__ void phase_pass(u64* r, u64 C, u64 D) {
    #pragma unroll
    for (int k = 0; k < 16; ++k)
        r[k] = ffma2(C, r[k], fmul2(D, swp(r[k])));
}

__device__ __forceinline__ u64 pair_apply(u64 a, u64 p, u64 cA, u64 dA, u64 cB, u64 dB) {
    return ffma2(cA, a, ffma2(dA, swp(a), ffma2(cB, p, fmul2(dB, swp(p)))));
}

// One variational layer: gates + transpose + store + compile-time-indexed gather.
template<int PAR>
__device__ __forceinline__ void layer_body(u64* r, u64* sc, u64* scw,
                                           const u64* __restrict__ GB,
                                           const u64* __restrict__ pre,
                                           const u64* __restrict__ ppk,   // [2][16][2] flat
                                           unsigned SB, unsigned Bg,
                                           unsigned TA, unsigned C2,
                                           int lane, int w, bool skip_post) {
    // qubits 6..9: full complex gates on k bits (layout A)
    gate_reg<8>(r, GB + 23);
    gate_reg<4>(r, GB + 31);
    gate_reg<2>(r, GB + 39);
    gate_reg<1>(r, GB + 47);

    // q1..5 pre-diag (per-lane table) + q1 RY (lane bit 4, shuffle)
    phase_pass(r, pre[0], pre[1]);
    ry_shfl<16>(r, GB[8], (lane & 16) ? GB[9] : GB[10]);

    // in-warp transpose j[3:0] <-> j[7:4] (conflict-free XOR swizzle)
    #pragma unroll
    for (int k = 0; k < 16; ++k)
        scw[TA ^ (unsigned)k] = r[k];
    __syncwarp();
    #pragma unroll
    for (int k = 0; k < 16; ++k)
        r[k] = scw[C2 ^ (unsigned)(k * 17)];
    __syncwarp();

    // q2..5 RY butterflies on k bits (k bit 3 -> q2 ... bit 0 -> q5)
    ry_reg<8>(r, GB[11], GB[12], GB[13]);
    ry_reg<4>(r, GB[14], GB[15], GB[16]);
    ry_reg<2>(r, GB[17], GB[18], GB[19]);
    ry_reg<1>(r, GB[20], GB[21], GB[22]);

    // q1..5 post-diag from (b1,k)-indexed broadcast table; last layer: invisible to |amp|^2
    if (!skip_post) {
        const u64* pk = ppk + (((unsigned)lane >> 4) & 1u) * 32;
        #pragma unroll
        for (int k = 0; k < 16; ++k)
            r[k] = ffma2(pk[2 * k], r[k], fmul2(pk[2 * k + 1], swp(r[k])));
    }

    // store at A-swizzled TRUE-index addresses (transposed layout positions)
    #pragma unroll
    for (int k = 0; k < 16; ++k) {
        const unsigned K = ((unsigned)(k >> 1) << 5) | ((unsigned)(k & 1) << 4)
                         | (PAR ? ((unsigned)(k >> 1) << 1) : (unsigned)(k >> 1));
        sc[SB ^ K] = r[k];
    }
    __syncthreads();

    // gather: idx = Bg ^ K[i] (GF(2)-linear, all immediates; identical to R15)
    constexpr unsigned PC = PAR ? PC1 : PC0;
    constexpr unsigned K0[16] = {0x000,0x308, 0x003,0x30B, 0x006,0x30E, 0x005,0x30D,
                                 0x00C,0x304, 0x00F,0x307, 0x00A,0x302, 0x009,0x301};
    constexpr unsigned K1[16] = {0x000,0x022, 0x044,0x066, 0x088,0x0AA, 0x0CC,0x0EE,
                                 0x111,0x133, 0x155,0x177, 0x199,0x1BB, 0x1DD,0x1FF};
    const u64 q0_0 = GB[0], q0_1 = GB[1], q0_2 = GB[2], q0_3 = GB[3];
    const u64 q1_0 = GB[4], q1_1 = GB[5], q1_2 = GB[6], q1_3 = GB[7];

    if (PAR == 0) {
        const bool bw = (w != 0);
        const u64 cA0 = bw ? q1_0 : q0_0, dA0 = bw ? q1_1 : q0_1;
        const u64 cB0 = bw ? q1_2 : q0_2, dB0 = bw ? q1_3 : q0_3;
        const u64 cA1 = bw ? q0_0 : q1_0, dA1 = bw ? q0_1 : q1_1;
        const u64 cB1 = bw ? q0_2 : q1_2, dB1 = bw ? q0_3 : q1_3;
        #pragma unroll
        for (int c = 0; c < 8; ++c) {
            unsigned i0 = Bg ^ K0[2 * c];
            unsigned i1 = Bg ^ K0[2 * c + 1];
            r[2 * c]     = pair_apply(sc[i0], sc[i0 ^ PC], cA0, dA0, cB0, dB0);
            r[2 * c + 1] = pair_apply(sc[i1], sc[i1 ^ PC], cA1, dA1, cB1, dB1);
        }
    } else {
        const bool bb = (((lane ^ w) & 1) != 0);
        const u64 cA = bb ? q1_0 : q0_0, dA = bb ? q1_1 : q0_1;
        const u64 cB = bb ? q1_2 : q0_2, dB = bb ? q1_3 : q0_3;
        #pragma unroll
        for (int i = 0; i < 16; ++i) {
            unsigned idx = Bg ^ K1[i];
            r[i] = pair_apply(sc[idx], sc[idx ^ PC], cA, dA, cB, dB);
        }
    }
    __syncthreads();
}

__global__ __launch_bounds__(TPB, 12) void qsim_kernel(
    const float* __restrict__ x,     // (B, 2*NQ)
    float* __restrict__ out)         // (B, NQ)
{
    __shared__ __align__(16) u64 sc[DIM];             // 8 KB state scratch
    __shared__ __align__(16) u64 gmat_s[NL * GL + 1]; // 1.77 KB compact gates
    __shared__ __align__(16) u64 pp_s[NL][32][2];     // 2 KB pre packs
    __shared__ __align__(16) u64 ppk_s[NL][2][16][2]; // 2 KB post packs
    __shared__ float2 venc[NQ][2];
    __shared__ float red[2][NQ];

    const int t    = threadIdx.x;
    const int lane = t & 31;
    const int w    = t >> 5;                   // warp half = qubit-0 bit (j9)
    const int s    = blockIdx.x;
    const float inv_sqrt2 = 0.70710678118654752440f;
    const float pi_f      = 3.14159265358979323846f;

    // vectorized table copies
    {
        const uint4* gs = (const uint4*)&g_gmat2[0];
        uint4* gd = (uint4*)&gmat_s[0];
        #pragma unroll
        for (int i = t; i < (NL * GL + 1) / 2; i += TPB) gd[i] = gs[i];
        const uint4* ps = (const uint4*)&g_pp[0][0][0];
        uint4* pd = (uint4*)&pp_s[0][0][0];
        #pragma unroll
        for (int i = t; i < 128; i += TPB) pd[i] = ps[i];
        const uint4* ks = (const uint4*)&g_ppk[0][0][0][0];
        uint4* kd = (uint4*)&ppk_s[0][0][0][0];
        #pragma unroll
        for (int i = t; i < 128; i += TPB) kd[i] = ks[i];
    }

    const unsigned l15 = (unsigned)(lane & 15);
    const unsigned lhb = (unsigned)(lane >> 4);
    // transpose addressing constants
    const unsigned TA = ((unsigned)lane << 4) | l15;          // store: TA ^ k
    const unsigned C2 = (lhb << 8) | l15;                     // load:  C2 ^ (k*17)
    // store base constants (A-swizzled true-index): SB ^ Kst[k]
    const unsigned SBbase = ((((unsigned)w << 4) | (lhb << 3)) << 5) | l15;
    const unsigned SB0 = SBbase ^ (lhb ? A0_3 : 0u);
    const unsigned SB1 = SBbase ^ (lhb ? A1_3 : 0u) ^ (w ? A1_4 : 0u);

    // per-thread gather bases: XOR of addr-columns for lane bits (j4..j8) and w (j9)
    unsigned B0 = 0, B1 = 0;
    {
        if (lane & 1)  { B0 ^= 0x018u; B1 ^= 0x201u; }
        if (lane & 2)  { B0 ^= 0x031u; B1 ^= 0x023u; }
        if (lane & 4)  { B0 ^= 0x063u; B1 ^= 0x046u; }
        if (lane & 8)  { B0 ^= 0x0C6u; B1 ^= 0x08Cu; }
        if (lane & 16) { B0 ^= 0x18Du; B1 ^= 0x119u; }
        if (w)         { B0 ^= 0x309u; B1 ^= 0x211u; }
    }
    u64* scw = sc + ((unsigned)w << 9);

    if (t < NQ) {
        int q = t;
        float th = 0.5f * pi_f * (x[s * 2 * NQ + q]      + 1.0f);
        float ph = 0.5f * pi_f * (x[s * 2 * NQ + NQ + q] + 1.0f);
        float st, ct; sincosf(0.5f * th, &st, &ct);
        float sh, ch; sincosf(0.5f * ph, &sh, &ch);
        float a = inv_sqrt2 * (ct - st);
        float b = inv_sqrt2 * (ct + st);
        venc[q][0] = make_float2(a * ch, -a * sh);
        venc[q][1] = make_float2(b * ch,  b * sh);
    }
    __syncthreads();

    // ---- build product state: j = w*512 + lane*16 + k ; qubit q <-> j bit (9-q) ----
    u64 r[16];
    {
        float2 L = venc[0][w];
        L = cmulf(L, venc[1][(lane >> 4) & 1]);
        L = cmulf(L, venc[2][(lane >> 3) & 1]);
        L = cmulf(L, venc[3][(lane >> 2) & 1]);
        L = cmulf(L, venc[4][(lane >> 1) & 1]);
        L = cmulf(L, venc[5][lane & 1]);
        float2 RH[4], RL[4];
        #pragma unroll
        for (int h = 0; h < 4; ++h) RH[h] = cmulf(venc[6][(h >> 1) & 1], venc[7][h & 1]);
        #pragma unroll
        for (int l = 0; l < 4; ++l) RL[l] = cmulf(venc[8][(l >> 1) & 1], venc[9][l & 1]);
        #pragma unroll
        for (int k = 0; k < 16; ++k) {
            float2 a = cmulf(L, cmulf(RH[k >> 2], RL[k & 3]));
            r[k] = pack2(a.x, a.y);
        }
    }

    // ---- layers: loop over layer-PAIRS (body fits L1.5 I$) ----
    #pragma unroll 1
    for (int it = 0; it < 2; ++it) {
        const int l0 = 2 * it, l1 = 2 * it + 1;
        layer_body<0>(r, sc, scw, &gmat_s[l0 * GL], pp_s[l0][lane],
                      &ppk_s[l0][0][0][0], SB0, B0, TA, C2, lane, w, false);
        layer_body<1>(r, sc, scw, &gmat_s[l1 * GL], pp_s[l1][lane],
                      &ppk_s[l1][0][0][0], SB1, B1, TA, C2, lane, w, it == 1);
    }

    // ---- <Z_q> readout ----
    u64 tot = 0, accP[4] = {0,0,0,0}, accN[4] = {0,0,0,0};
    #pragma unroll
    for (int k = 0; k < 16; ++k) {
        u64 sq = fmul2(r[k], r[k]);          // (re^2, im^2)
        tot = fadd2(tot, sq);
        #pragma unroll
        for (int b = 0; b < 4; ++b) {
            if ((k >> b) & 1) accN[b] = fadd2(accN[b], sq);
            else              accP[b] = fadd2(accP[b], sq);
        }
    }
    float zq[NQ];
    {
        float tl, th; unpk(tot, tl, th);
        float pr_tot = tl + th;
        zq[0] = w ? -pr_tot : pr_tot;
        zq[1] = (lane & 16) ? -pr_tot : pr_tot;
        zq[2] = (lane & 8)  ? -pr_tot : pr_tot;
        zq[3] = (lane & 4)  ? -pr_tot : pr_tot;
        zq[4] = (lane & 2)  ? -pr_tot : pr_tot;
        zq[5] = (lane & 1)  ? -pr_tot : pr_tot;
        #pragma unroll
        for (int b = 0; b < 4; ++b) {        // k bit b <-> qubit 9-b
            float pl, ph, nl, nh;
            unpk(accP[b], pl, ph); unpk(accN[b], nl, nh);
            zq[9 - b] = (pl + ph) - (nl + nh);
        }
    }
    #pragma unroll
    for (int q = 0; q < NQ; ++q) {
        #pragma unroll
        for (int o = 16; o > 0; o >>= 1)
            zq[q] += __shfl_xor_sync(0xffffffffu, zq[q], o);
    }
    if (lane == 0) {
        #pragma unroll
        for (int q = 0; q < NQ; ++q) red[w][q] = zq[q];
    }
    __syncthreads();
    if (t < NQ)
        out[s * NQ + t] = red[0][t] + red[1][t];
}

extern "C" void kernel_launch(void* const* d_in, const int* in_sizes, int n_in,
                              void* d_out, int out_size) {
    const float* x = (const float*)d_in[0];
    const float* w = (const float*)d_in[1];
    float* out = (float*)d_out;
    int B = in_sizes[0] / (2 * NQ);   // 4096 flattened samples
    precompute_kernel<<<1, 128>>>(w);
    qsim_kernel<<<B, TPB>>>(x, out);
}